// round 2
// baseline (speedup 1.0000x reference)
#include <cuda_runtime.h>
#include <cstdint>

#define W_IMG 512
#define H_IMG 512
#define HW    (512*512)
#define NB    4
#define EPS   1e-5f

#define TILE_W 128
#define TILE_H 8
#define BX 32
#define BY 8
#define NTHREADS (BX*BY)
#define PPT 4
#define HALO 2
#define SM_W (TILE_W + 2*HALO)   // 132
#define SM_H (TILE_H + 2*HALO)   // 12

#define GMAX_BPB 32                                         // gray-max blocks per batch
#define NBLK_MAIN (NB * (H_IMG/TILE_H) * (W_IMG/TILE_W))    // 4*64*4 = 1024

// scratch (no device allocs allowed) — every slot rewritten each replay, no init needed
__device__ float g_gmax_partial[NB * GMAX_BPB];
__device__ float g_blockA[NBLK_MAIN];
__device__ float g_blockB[NBLK_MAIN];

// ---- packed f32x2 helpers (sm_103a FFMA2 — ptxas never emits these from C++) ----
__device__ __forceinline__ unsigned long long pack2(float lo, float hi) {
    unsigned long long d;
    asm("mov.b64 %0, {%1, %2};" : "=l"(d)
        : "r"(__float_as_uint(lo)), "r"(__float_as_uint(hi)));
    return d;
}
__device__ __forceinline__ void unpack2(unsigned long long v, float& lo, float& hi) {
    unsigned int a, b;
    asm("mov.b64 {%0, %1}, %2;" : "=r"(a), "=r"(b) : "l"(v));
    lo = __uint_as_float(a); hi = __uint_as_float(b);
}
__device__ __forceinline__ unsigned long long fma2(unsigned long long a,
                                                   unsigned long long b,
                                                   unsigned long long c) {
    unsigned long long d;
    asm("fma.rn.f32x2 %0, %1, %2, %3;" : "=l"(d) : "l"(a), "l"(b), "l"(c));
    return d;
}
__device__ __forceinline__ unsigned long long mul2(unsigned long long a,
                                                   unsigned long long b) {
    unsigned long long d;
    asm("mul.rn.f32x2 %0, %1, %2;" : "=l"(d) : "l"(a), "l"(b));
    return d;
}

// ---- per-block partial max of hdr_original_gray (values >= 0) ----
__global__ void graymax_partial_kernel(const float* __restrict__ gray) {
    const int b     = blockIdx.x / GMAX_BPB;
    const int chunk = blockIdx.x - b * GMAX_BPB;
    const int t     = threadIdx.x;                    // 256 threads
    const float4* p4 = reinterpret_cast<const float4*>(gray + (size_t)b * HW);
    const int base = chunk * 2048;                    // 2048 float4 per block
    float m = 0.0f;
#pragma unroll
    for (int k = 0; k < 8; k++) {
        float4 v = p4[base + t + k * 256];
        m = fmaxf(m, fmaxf(fmaxf(v.x, v.y), fmaxf(v.z, v.w)));
    }
#pragma unroll
    for (int o = 16; o > 0; o >>= 1)
        m = fmaxf(m, __shfl_down_sync(0xFFFFFFFFu, m, o));
    __shared__ float red[8];
    if ((t & 31) == 0) red[t >> 5] = m;
    __syncthreads();
    if (t < 8) {
        m = red[t];
#pragma unroll
        for (int o = 4; o > 0; o >>= 1)
            m = fmaxf(m, __shfl_down_sync(0xFFu, m, o));
        if (t == 0) g_gmax_partial[blockIdx.x] = m;
    }
}

__global__ __launch_bounds__(NTHREADS, 2)
void intensity_loss_main(const float* __restrict__ fake,
                         const float* __restrict__ gamma_hdr,
                         const float* __restrict__ hdr_im,
                         const float* __restrict__ r_weights,
                         const float* __restrict__ f_factors) {
    __shared__ __align__(16) float sf[SM_H * SM_W];
    __shared__ __align__(16) float sg[SM_H * SM_W];
    __shared__ __align__(16) float sh[SM_H * SM_W];
    __shared__ float redA[BY], redB[BY];
    __shared__ float s_gmax;

    const int b     = blockIdx.z;
    const int wbase = blockIdx.x * TILE_W;
    const int hbase = blockIdx.y * TILE_H;
    const int tid   = threadIdx.y * BX + threadIdx.x;

    const float ff   = f_factors[b];
    const float expo = 1.0f - ff;

    const float* fp = fake      + (size_t)b * HW;
    const float* gp = gamma_hdr + (size_t)b * HW;
    const float* hp = hdr_im    + (size_t)b * HW;

    // warp 0: finish the gray-max reduction for this batch
    if (tid < 32) {
        float m = g_gmax_partial[b * GMAX_BPB + tid];
#pragma unroll
        for (int o = 16; o > 0; o >>= 1)
            m = fmaxf(m, __shfl_down_sync(0xFFFFFFFFu, m, o));
        if (tid == 0) s_gmax = m;
    }

    // stage tile + halo (zero-pad OOB); hdr gets pow applied here
    for (int i = tid; i < SM_H * SM_W; i += NTHREADS) {
        const int r  = i / SM_W;
        const int c  = i - r * SM_W;
        const int gh = hbase + r - HALO;
        const int gw = wbase + c - HALO;
        float vf = 0.0f, vg = 0.0f, vh = 0.0f;
        if (gh >= 0 && gh < H_IMG && gw >= 0 && gw < W_IMG) {
            const int gi = gh * W_IMG + gw;
            vf = fp[gi];
            vg = gp[gi];
            vh = __powf(hp[gi], expo);
        }
        sf[i] = vf; sg[i] = vg; sh[i] = vh;
    }
    __syncthreads();

    const float cobj = s_gmax / ff;   // ALPHA = 1

    const int lw  = threadIdx.x * PPT;
    const int lh  = threadIdx.y;
    const int gw0 = wbase + lw;
    const int gh  = hbase + lh;
    const float* rwp = r_weights + (size_t)b * 25 * HW + (size_t)gh * W_IMG + gw0;

    // packed accumulators: lanes = (f, g) / (f^2, g^2) / (h, 1) per pixel
    unsigned long long s1fg[PPT], s2fg[PPT], shw[PPT];
#pragma unroll
    for (int l = 0; l < PPT; l++) { s1fg[l] = 0ull; s2fg[l] = 0ull; shw[l] = 0ull; }

#pragma unroll
    for (int di = 0; di < 5; di++) {
        const int rowoff = (lh + di) * SM_W + lw;   // 16B-aligned
        const float4 f0 = *reinterpret_cast<const float4*>(&sf[rowoff]);
        const float4 f1 = *reinterpret_cast<const float4*>(&sf[rowoff + 4]);
        const float4 g0 = *reinterpret_cast<const float4*>(&sg[rowoff]);
        const float4 g1 = *reinterpret_cast<const float4*>(&sg[rowoff + 4]);
        const float4 h0 = *reinterpret_cast<const float4*>(&sh[rowoff]);
        const float4 h1 = *reinterpret_cast<const float4*>(&sh[rowoff + 4]);
        const float xf[8] = {f0.x, f0.y, f0.z, f0.w, f1.x, f1.y, f1.z, f1.w};
        const float xg[8] = {g0.x, g0.y, g0.z, g0.w, g1.x, g1.y, g1.z, g1.w};
        const float xh[8] = {h0.x, h0.y, h0.z, h0.w, h1.x, h1.y, h1.z, h1.w};

        unsigned long long xfg[8], x2[8], xh1[8];
#pragma unroll
        for (int j = 0; j < 8; j++) {
            xfg[j] = pack2(xf[j], xg[j]);
            x2[j]  = mul2(xfg[j], xfg[j]);
            xh1[j] = pack2(xh[j], 1.0f);
        }

#pragma unroll
        for (int dj = 0; dj < 5; dj++) {
            const float4 rw4 = *reinterpret_cast<const float4*>(rwp + (size_t)(di * 5 + dj) * HW);
            const float rwa[PPT] = {rw4.x, rw4.y, rw4.z, rw4.w};
#pragma unroll
            for (int l = 0; l < PPT; l++) {
                const unsigned long long w2 = pack2(rwa[l], rwa[l]);
                s1fg[l] = fma2(w2, xfg[dj + l], s1fg[l]);
                s2fg[l] = fma2(w2, x2[dj + l],  s2fg[l]);
                shw[l]  = fma2(w2, xh1[dj + l], shw[l]);
            }
        }
    }

    // epilogue: per-pixel scalar, accumulate two sums
    float accA = 0.0f, accB = 0.0f;
#pragma unroll
    for (int l = 0; l < PPT; l++) {
        float s1f, s1g, s2f, s2g, s1h, ws;
        unpack2(s1fg[l], s1f, s1g);
        unpack2(s2fg[l], s2f, s2g);
        unpack2(shw[l],  s1h, ws);
        const float inv  = 1.0f / ws;
        const float muf  = s1f * inv;
        const float vrf  = fmaxf(s2f * inv - muf * muf, 0.0f);
        const float stdf = sqrtf(vrf + EPS);
        const float mug  = s1g * inv;
        const float vrg  = fmaxf(s2g * inv - mug * mug, 0.0f);
        const float stdg = sqrtf(vrg + EPS);
        const float muh  = s1h * inv;
        const float obj  = cobj * stdg * (muh + EPS);
        const float r    = 1.0f - stdf / (stdf + obj);
        const float wblf = ws - 1.0f;
        accA = fmaf(r, wblf, accA);
        accB += wblf;
    }

    // block reduction -> per-block partials (no atomics, no init)
#pragma unroll
    for (int o = 16; o > 0; o >>= 1) {
        accA += __shfl_down_sync(0xFFFFFFFFu, accA, o);
        accB += __shfl_down_sync(0xFFFFFFFFu, accB, o);
    }
    const int wid = tid >> 5, lane = tid & 31;
    if (lane == 0) { redA[wid] = accA; redB[wid] = accB; }
    __syncthreads();
    if (wid == 0) {
        accA = (lane < BY) ? redA[lane] : 0.0f;
        accB = (lane < BY) ? redB[lane] : 0.0f;
#pragma unroll
        for (int o = 4; o > 0; o >>= 1) {
            accA += __shfl_down_sync(0xFFFFFFFFu, accA, o);
            accB += __shfl_down_sync(0xFFFFFFFFu, accB, o);
        }
        if (lane == 0) {
            const int flat = (blockIdx.z * gridDim.y + blockIdx.y) * gridDim.x + blockIdx.x;
            g_blockA[flat] = accA;
            g_blockB[flat] = accB;
        }
    }
}

__global__ void finalize_kernel(float* __restrict__ out) {
    const int t = threadIdx.x;   // 512 threads, NBLK_MAIN = 1024
    float a = g_blockA[t] + g_blockA[t + 512];
    float bsum = g_blockB[t] + g_blockB[t + 512];
#pragma unroll
    for (int o = 16; o > 0; o >>= 1) {
        a    += __shfl_down_sync(0xFFFFFFFFu, a, o);
        bsum += __shfl_down_sync(0xFFFFFFFFu, bsum, o);
    }
    __shared__ float rA[16], rB[16];
    const int wid = t >> 5, lane = t & 31;
    if (lane == 0) { rA[wid] = a; rB[wid] = bsum; }
    __syncthreads();
    if (wid == 0) {
        a    = (lane < 16) ? rA[lane] : 0.0f;
        bsum = (lane < 16) ? rB[lane] : 0.0f;
#pragma unroll
        for (int o = 8; o > 0; o >>= 1) {
            a    += __shfl_down_sync(0xFFFFFFFFu, a, o);
            bsum += __shfl_down_sync(0xFFFFFFFFu, bsum, o);
        }
        if (lane == 0) out[0] = a / bsum;
    }
}

extern "C" void kernel_launch(void* const* d_in, const int* in_sizes, int n_in,
                              void* d_out, int out_size) {
    const float* fake      = (const float*)d_in[0];
    const float* gamma_hdr = (const float*)d_in[1];
    const float* hdr_im    = (const float*)d_in[2];
    const float* r_weights = (const float*)d_in[3];
    const float* f_factors = (const float*)d_in[4];
    const float* gray      = (const float*)d_in[5];
    float* out = (float*)d_out;

    graymax_partial_kernel<<<NB * GMAX_BPB, 256>>>(gray);
    dim3 grid(W_IMG / TILE_W, H_IMG / TILE_H, NB);
    dim3 block(BX, BY);
    intensity_loss_main<<<grid, block>>>(fake, gamma_hdr, hdr_im, r_weights, f_factors);
    finalize_kernel<<<1, 512>>>(out);
}

// round 3
// speedup vs baseline: 1.0522x; 1.0522x over previous
#include <cuda_runtime.h>
#include <cstdint>

#define W_IMG 512
#define H_IMG 512
#define HW    (512*512)
#define NB    4
#define EPS   1e-5f

#define TILE_W 128
#define TILE_H 8
#define BX 32
#define BY 8
#define NTHREADS (BX*BY)
#define PPT 4
#define HALO 2
#define SM_W (TILE_W + 2*HALO)   // 132
#define SM_H (TILE_H + 2*HALO)   // 12

#define GMAX_BPB 64                                         // gray-max blocks per batch
#define NBLK_MAIN (NB * (H_IMG/TILE_H) * (W_IMG/TILE_W))    // 4*64*4 = 1024

// scratch (no device allocs allowed) — every slot rewritten each replay, no init needed
__device__ float g_gmax_partial[NB * GMAX_BPB];
__device__ float g_blockA[NBLK_MAIN];
__device__ float g_blockB[NBLK_MAIN];

// ---- per-block partial max of hdr_original_gray (values >= 0) ----
__global__ void graymax_partial_kernel(const float* __restrict__ gray) {
    // trigger immediately: lets the PDL-launched main kernel start now
    cudaTriggerProgrammaticLaunchCompletion();

    const int b     = blockIdx.x >> 6;             // 64 blocks per batch
    const int chunk = blockIdx.x & 63;
    const int t     = threadIdx.x;                 // 256 threads
    const float4* p4 = reinterpret_cast<const float4*>(gray + (size_t)b * HW);
    const int base = chunk * 1024;                 // 1024 float4 per block
    float m = 0.0f;
#pragma unroll
    for (int k = 0; k < 4; k++) {
        float4 v = p4[base + t + k * 256];
        m = fmaxf(m, fmaxf(fmaxf(v.x, v.y), fmaxf(v.z, v.w)));
    }
#pragma unroll
    for (int o = 16; o > 0; o >>= 1)
        m = fmaxf(m, __shfl_down_sync(0xFFFFFFFFu, m, o));
    __shared__ float red[8];
    if ((t & 31) == 0) red[t >> 5] = m;
    __syncthreads();
    if (t < 8) {
        m = red[t];
#pragma unroll
        for (int o = 4; o > 0; o >>= 1)
            m = fmaxf(m, __shfl_down_sync(0xFFu, m, o));
        if (t == 0) g_gmax_partial[blockIdx.x] = m;
    }
}

__global__ __launch_bounds__(NTHREADS, 2)
void intensity_loss_main(const float* __restrict__ fake,
                         const float* __restrict__ gamma_hdr,
                         const float* __restrict__ hdr_im,
                         const float* __restrict__ r_weights,
                         const float* __restrict__ f_factors) {
    // trigger immediately: lets the PDL-launched finalize kernel spin up early
    cudaTriggerProgrammaticLaunchCompletion();

    __shared__ __align__(16) float sf[SM_H * SM_W];
    __shared__ __align__(16) float sg[SM_H * SM_W];
    __shared__ __align__(16) float sh[SM_H * SM_W];
    __shared__ float redA[BY], redB[BY];
    __shared__ float s_gmax;

    const int b     = blockIdx.z;
    const int wbase = blockIdx.x * TILE_W;
    const int hbase = blockIdx.y * TILE_H;
    const int tid   = threadIdx.y * BX + threadIdx.x;

    const float ff   = f_factors[b];
    const float expo = 1.0f - ff;

    const float* fp = fake      + (size_t)b * HW;
    const float* gp = gamma_hdr + (size_t)b * HW;
    const float* hp = hdr_im    + (size_t)b * HW;

    // stage tile + halo (zero-pad OOB); hdr gets pow applied here
    for (int i = tid; i < SM_H * SM_W; i += NTHREADS) {
        const int r  = i / SM_W;
        const int c  = i - r * SM_W;
        const int gh = hbase + r - HALO;
        const int gw = wbase + c - HALO;
        float vf = 0.0f, vg = 0.0f, vh = 0.0f;
        if (gh >= 0 && gh < H_IMG && gw >= 0 && gw < W_IMG) {
            const int gi = gh * W_IMG + gw;
            vf = fp[gi];
            vg = gp[gi];
            vh = __powf(hp[gi], expo);
        }
        sf[i] = vf; sg[i] = vg; sh[i] = vh;
    }
    __syncthreads();

    const int lw  = threadIdx.x * PPT;
    const int lh  = threadIdx.y;
    const int gw0 = wbase + lw;
    const int gh  = hbase + lh;
    const float* rwp = r_weights + (size_t)b * 25 * HW + (size_t)gh * W_IMG + gw0;

    float s1f[PPT] = {0,0,0,0}, s2f[PPT] = {0,0,0,0};
    float s1g[PPT] = {0,0,0,0}, s2g[PPT] = {0,0,0,0};
    float s1h[PPT] = {0,0,0,0}, ws [PPT] = {0,0,0,0};

#pragma unroll
    for (int di = 0; di < 5; di++) {
        const int rowoff = (lh + di) * SM_W + lw;   // 16B-aligned
        const float4 f0 = *reinterpret_cast<const float4*>(&sf[rowoff]);
        const float4 f1 = *reinterpret_cast<const float4*>(&sf[rowoff + 4]);
        const float4 g0 = *reinterpret_cast<const float4*>(&sg[rowoff]);
        const float4 g1 = *reinterpret_cast<const float4*>(&sg[rowoff + 4]);
        const float4 h0 = *reinterpret_cast<const float4*>(&sh[rowoff]);
        const float4 h1 = *reinterpret_cast<const float4*>(&sh[rowoff + 4]);
        const float xf[8] = {f0.x, f0.y, f0.z, f0.w, f1.x, f1.y, f1.z, f1.w};
        const float xg[8] = {g0.x, g0.y, g0.z, g0.w, g1.x, g1.y, g1.z, g1.w};
        const float xh[8] = {h0.x, h0.y, h0.z, h0.w, h1.x, h1.y, h1.z, h1.w};
#pragma unroll
        for (int dj = 0; dj < 5; dj++) {
            const float4 rw4 = *reinterpret_cast<const float4*>(rwp + (size_t)(di * 5 + dj) * HW);
            const float rwa[PPT] = {rw4.x, rw4.y, rw4.z, rw4.w};
#pragma unroll
            for (int l = 0; l < PPT; l++) {
                const float w = rwa[l];
                ws[l] += w;
                const float a = xf[dj + l];
                s1f[l] = fmaf(w, a, s1f[l]);
                s2f[l] = fmaf(w * a, a, s2f[l]);
                const float gq = xg[dj + l];
                s1g[l] = fmaf(w, gq, s1g[l]);
                s2g[l] = fmaf(w * gq, gq, s2g[l]);
                const float hq = xh[dj + l];
                s1h[l] = fmaf(w, hq, s1h[l]);
            }
        }
    }

    // ---- now (and only now) we need the gray-max: wait for graymax kernel ----
    cudaGridDependencySynchronize();
    if (tid < 32) {
        float m = fmaxf(g_gmax_partial[b * GMAX_BPB + tid],
                        g_gmax_partial[b * GMAX_BPB + 32 + tid]);
#pragma unroll
        for (int o = 16; o > 0; o >>= 1)
            m = fmaxf(m, __shfl_down_sync(0xFFFFFFFFu, m, o));
        if (tid == 0) s_gmax = m;
    }
    __syncthreads();
    const float cobj = s_gmax / ff;   // ALPHA = 1

    // ---- epilogue: per-pixel scalar, accumulate two sums ----
    float accA = 0.0f, accB = 0.0f;
#pragma unroll
    for (int l = 0; l < PPT; l++) {
        const float inv  = 1.0f / ws[l];
        const float muf  = s1f[l] * inv;
        const float vrf  = fmaxf(s2f[l] * inv - muf * muf, 0.0f);
        const float stdf = sqrtf(vrf + EPS);
        const float mug  = s1g[l] * inv;
        const float vrg  = fmaxf(s2g[l] * inv - mug * mug, 0.0f);
        const float stdg = sqrtf(vrg + EPS);
        const float muh  = s1h[l] * inv;
        const float obj  = cobj * stdg * (muh + EPS);
        const float r    = 1.0f - stdf / (stdf + obj);
        const float wblf = ws[l] - 1.0f;
        accA = fmaf(r, wblf, accA);
        accB += wblf;
    }

    // block reduction -> per-block partials (no atomics, no init)
#pragma unroll
    for (int o = 16; o > 0; o >>= 1) {
        accA += __shfl_down_sync(0xFFFFFFFFu, accA, o);
        accB += __shfl_down_sync(0xFFFFFFFFu, accB, o);
    }
    const int wid = tid >> 5, lane = tid & 31;
    if (lane == 0) { redA[wid] = accA; redB[wid] = accB; }
    __syncthreads();
    if (wid == 0) {
        accA = (lane < BY) ? redA[lane] : 0.0f;
        accB = (lane < BY) ? redB[lane] : 0.0f;
#pragma unroll
        for (int o = 4; o > 0; o >>= 1) {
            accA += __shfl_down_sync(0xFFFFFFFFu, accA, o);
            accB += __shfl_down_sync(0xFFFFFFFFu, accB, o);
        }
        if (lane == 0) {
            const int flat = (blockIdx.z * gridDim.y + blockIdx.y) * gridDim.x + blockIdx.x;
            g_blockA[flat] = accA;
            g_blockB[flat] = accB;
        }
    }
}

__global__ void finalize_kernel(float* __restrict__ out) {
    // PDL: we were launched early; wait until main kernel's partials are visible
    cudaGridDependencySynchronize();

    const int t = threadIdx.x;   // 512 threads, NBLK_MAIN = 1024
    float a    = g_blockA[t] + g_blockA[t + 512];
    float bsum = g_blockB[t] + g_blockB[t + 512];
#pragma unroll
    for (int o = 16; o > 0; o >>= 1) {
        a    += __shfl_down_sync(0xFFFFFFFFu, a, o);
        bsum += __shfl_down_sync(0xFFFFFFFFu, bsum, o);
    }
    __shared__ float rA[16], rB[16];
    const int wid = t >> 5, lane = t & 31;
    if (lane == 0) { rA[wid] = a; rB[wid] = bsum; }
    __syncthreads();
    if (wid == 0) {
        a    = (lane < 16) ? rA[lane] : 0.0f;
        bsum = (lane < 16) ? rB[lane] : 0.0f;
#pragma unroll
        for (int o = 8; o > 0; o >>= 1) {
            a    += __shfl_down_sync(0xFFFFFFFFu, a, o);
            bsum += __shfl_down_sync(0xFFFFFFFFu, bsum, o);
        }
        if (lane == 0) out[0] = a / bsum;
    }
}

extern "C" void kernel_launch(void* const* d_in, const int* in_sizes, int n_in,
                              void* d_out, int out_size) {
    const float* fake      = (const float*)d_in[0];
    const float* gamma_hdr = (const float*)d_in[1];
    const float* hdr_im    = (const float*)d_in[2];
    const float* r_weights = (const float*)d_in[3];
    const float* f_factors = (const float*)d_in[4];
    const float* gray      = (const float*)d_in[5];
    float* out = (float*)d_out;

    // k1: gray-max partials (plain launch)
    {
        cudaLaunchConfig_t cfg = {};
        cfg.gridDim  = dim3(NB * GMAX_BPB);
        cfg.blockDim = dim3(256);
        cudaLaunchKernelEx(&cfg, graymax_partial_kernel, gray);
    }
    // k2: main, PDL — overlaps with graymax, gridsyncs before epilogue
    {
        cudaLaunchAttribute attr;
        attr.id = cudaLaunchAttributeProgrammaticStreamSerialization;
        attr.val.programmaticStreamSerializationAllowed = 1;
        cudaLaunchConfig_t cfg = {};
        cfg.gridDim  = dim3(W_IMG / TILE_W, H_IMG / TILE_H, NB);
        cfg.blockDim = dim3(BX, BY);
        cfg.attrs    = &attr;
        cfg.numAttrs = 1;
        cudaLaunchKernelEx(&cfg, intensity_loss_main,
                           fake, gamma_hdr, hdr_im, r_weights, f_factors);
    }
    // k3: finalize, PDL — launch latency hidden behind main's tail
    {
        cudaLaunchAttribute attr;
        attr.id = cudaLaunchAttributeProgrammaticStreamSerialization;
        attr.val.programmaticStreamSerializationAllowed = 1;
        cudaLaunchConfig_t cfg = {};
        cfg.gridDim  = dim3(1);
        cfg.blockDim = dim3(512);
        cfg.attrs    = &attr;
        cfg.numAttrs = 1;
        cudaLaunchKernelEx(&cfg, finalize_kernel, out);
    }
}